// round 3
// baseline (speedup 1.0000x reference)
#include <cuda_runtime.h>
#include <cstdint>

#define NN  100000
#define DD  128
#define EE  3200000
#define NTILES (NN / 32)   // 3125, exact

// Scratch (no allocs allowed): 51.2MB h + deg/dinv
__device__ float g_deg[NN];
__device__ float g_dinv[NN];
__device__ float g_h[(size_t)NN * DD];

// ---------------------------------------------------------------------------
// K0: deg[i] = 1.0 (self-loop weight folded into init)
// ---------------------------------------------------------------------------
__global__ void k_init_deg() {
    int i = blockIdx.x * blockDim.x + threadIdx.x;
    if (i < NN) g_deg[i] = 1.0f;
}

// ---------------------------------------------------------------------------
// K1: deg[dst] += w  over all edges (edge_index is int32!)
// ---------------------------------------------------------------------------
__global__ void k_deg(const int* __restrict__ dst,
                      const float* __restrict__ w, int E) {
    int e = blockIdx.x * blockDim.x + threadIdx.x;
    if (e < E) {
        unsigned d = (unsigned)dst[e];
        if (d < NN) atomicAdd(&g_deg[d], w[e]);
    }
}

// ---------------------------------------------------------------------------
// K2: dinv = rsqrt(deg)
// ---------------------------------------------------------------------------
__global__ void k_dinv() {
    int i = blockIdx.x * blockDim.x + threadIdx.x;
    if (i < NN) {
        float d = g_deg[i];
        g_dinv[i] = (d > 0.0f) ? rsqrtf(d) : 0.0f;
    }
}

// ---------------------------------------------------------------------------
// K3: h = x @ W ; out = b + dinv^2 * h   (self-loop term + bias, full init)
// Block: 256 threads. Dynamic smem: W (64KB) + 32-row x tile (16KB).
// ---------------------------------------------------------------------------
__global__ void k_gemm(const float* __restrict__ x,
                       const float* __restrict__ W,
                       const float* __restrict__ b,
                       float* __restrict__ out) {
    extern __shared__ char smem[];
    float4* Ws = (float4*)smem;                 // [128][32] float4  = 64KB
    float*  Xs = (float*)(smem + 64 * 1024);    // [32][128] float   = 16KB

    const int t = threadIdx.x;
    const int c = t & 31;
    const int r = t >> 5;

    const float4* W4 = (const float4*)W;
    #pragma unroll
    for (int i = 0; i < 16; i++) Ws[t + i * 256] = W4[t + i * 256];

    const float4 b4 = ((const float4*)b)[c];

    for (int tile = blockIdx.x; tile < NTILES; tile += gridDim.x) {
        const int row0 = tile * 32;

        __syncthreads();   // protect Xs from previous iteration's readers
        const float4* X4 = (const float4*)(x + (size_t)row0 * DD);
        float4* Xs4 = (float4*)Xs;
        #pragma unroll
        for (int i = 0; i < 4; i++) Xs4[t + i * 256] = X4[t + i * 256];
        __syncthreads();

        float4 acc0 = make_float4(0.f, 0.f, 0.f, 0.f);
        float4 acc1 = make_float4(0.f, 0.f, 0.f, 0.f);
        float4 acc2 = make_float4(0.f, 0.f, 0.f, 0.f);
        float4 acc3 = make_float4(0.f, 0.f, 0.f, 0.f);

        #pragma unroll 8
        for (int k = 0; k < DD; k++) {
            const float4 w4 = Ws[k * 32 + c];
            const float x0 = Xs[(r     ) * DD + k];
            const float x1 = Xs[(r +  8) * DD + k];
            const float x2 = Xs[(r + 16) * DD + k];
            const float x3 = Xs[(r + 24) * DD + k];
            acc0.x += x0 * w4.x; acc0.y += x0 * w4.y; acc0.z += x0 * w4.z; acc0.w += x0 * w4.w;
            acc1.x += x1 * w4.x; acc1.y += x1 * w4.y; acc1.z += x1 * w4.z; acc1.w += x1 * w4.w;
            acc2.x += x2 * w4.x; acc2.y += x2 * w4.y; acc2.z += x2 * w4.z; acc2.w += x2 * w4.w;
            acc3.x += x3 * w4.x; acc3.y += x3 * w4.y; acc3.z += x3 * w4.z; acc3.w += x3 * w4.w;
        }

        float4 accs[4] = {acc0, acc1, acc2, acc3};
        #pragma unroll
        for (int m = 0; m < 4; m++) {
            const int row = row0 + r + 8 * m;
            const float di = g_dinv[row];
            const float n2 = di * di;
            ((float4*)(g_h + (size_t)row * DD))[c] = accs[m];
            float4 o;
            o.x = b4.x + n2 * accs[m].x;
            o.y = b4.y + n2 * accs[m].y;
            o.z = b4.z + n2 * accs[m].z;
            o.w = b4.w + n2 * accs[m].w;
            ((float4*)(out + (size_t)row * DD))[c] = o;
        }
    }
}

// ---------------------------------------------------------------------------
// K4: edge scatter. One warp per edge: gather h[src] row (float4/lane),
// scale by norm, vectorized atomic add into out[dst].
// ---------------------------------------------------------------------------
__global__ void k_scatter(const int* __restrict__ src,
                          const int* __restrict__ dst,
                          const float* __restrict__ w,
                          float* __restrict__ out, int E) {
    const int warp = (blockIdx.x * blockDim.x + threadIdx.x) >> 5;
    const int lane = threadIdx.x & 31;
    if (warp >= E) return;

    const unsigned s = (unsigned)src[warp];
    const unsigned d = (unsigned)dst[warp];
    if (s >= NN || d >= NN) return;   // guard: degrade to rel_err, not crash
    const float norm = g_dinv[s] * w[warp] * g_dinv[d];

    const float4 v = ((const float4*)(g_h + (size_t)s * DD))[lane];
    float* o = out + (size_t)d * DD + lane * 4;
    asm volatile("red.global.add.v4.f32 [%0], {%1, %2, %3, %4};"
                 :: "l"(o),
                    "f"(v.x * norm), "f"(v.y * norm),
                    "f"(v.z * norm), "f"(v.w * norm)
                 : "memory");
}

// ---------------------------------------------------------------------------
extern "C" void kernel_launch(void* const* d_in, const int* in_sizes, int n_in,
                              void* d_out, int out_size) {
    // Bind inputs by unique element count (robust to metadata ordering):
    //   x = 12,800,000 | edge_index = 6,400,000 (int32) | edge_weight = 3,200,000
    //   W = 16,384     | b = 128
    const float* x  = nullptr;
    const int*   ei = nullptr;
    const float* ew = nullptr;
    const float* W  = nullptr;
    const float* b  = nullptr;
    int E = 0;
    for (int i = 0; i < n_in; i++) {
        const int sz = in_sizes[i];
        if      (sz == NN * DD)   x  = (const float*)d_in[i];
        else if (sz == 2 * EE)    ei = (const int*)d_in[i];
        else if (sz == EE)        { ew = (const float*)d_in[i]; E = sz; }
        else if (sz == DD * DD)   W  = (const float*)d_in[i];
        else if (sz == DD)        b  = (const float*)d_in[i];
    }
    if (!x || !ei || !ew || !W || !b) return;

    float* out = (float*)d_out;
    const int* src = ei;
    const int* dst = ei + E;

    k_init_deg<<<(NN + 255) / 256, 256>>>();
    k_deg<<<(E + 255) / 256, 256>>>(dst, ew, E);
    k_dinv<<<(NN + 255) / 256, 256>>>();

    static bool attr_set = false;
    if (!attr_set) {
        cudaFuncSetAttribute(k_gemm, cudaFuncAttributeMaxDynamicSharedMemorySize,
                             80 * 1024);
        attr_set = true;
    }
    k_gemm<<<296, 256, 80 * 1024>>>(x, W, b, out);

    const int edges_per_block = 8;  // 256 threads / 32
    k_scatter<<<(E + edges_per_block - 1) / edges_per_block, 256>>>(src, dst, ew, out, E);
}

// round 4
// speedup vs baseline: 1.2798x; 1.2798x over previous
#include <cuda_runtime.h>
#include <cstdint>

#define NN  100000
#define DD  128
#define EE  3200000
#define NTILES (NN / 32)   // 3125, exact
#define SCAN_T 1024
#define CH ((NN + SCAN_T - 1) / SCAN_T)   // 98

// Scratch (static device arrays; no allocs allowed)
__device__ float g_deg[NN];
__device__ float g_dinv[NN];
__device__ float g_h[(size_t)NN * DD];        // 51.2 MB
__device__ int   g_count[NN];
__device__ int   g_off[NN + 1];
__device__ int   g_cur[NN];
__device__ int   g_csr_src[EE];               // 12.8 MB
__device__ float g_csr_norm[EE];              // 12.8 MB

// ---------------------------------------------------------------------------
// K0: deg[i] = 1.0 (self-loop folded in), count[i] = 0
// ---------------------------------------------------------------------------
__global__ void k_init() {
    int i = blockIdx.x * blockDim.x + threadIdx.x;
    if (i < NN) { g_deg[i] = 1.0f; g_count[i] = 0; }
}

// ---------------------------------------------------------------------------
// K1: deg[dst] += w ; count[dst] += 1
// ---------------------------------------------------------------------------
__global__ void k_deg_count(const int* __restrict__ dst,
                            const float* __restrict__ w, int E) {
    int e = blockIdx.x * blockDim.x + threadIdx.x;
    if (e < E) {
        unsigned d = (unsigned)dst[e];
        if (d < NN) {
            atomicAdd(&g_deg[d], w[e]);
            atomicAdd(&g_count[d], 1);
        }
    }
}

// ---------------------------------------------------------------------------
// K2: dinv = rsqrt(deg)
// ---------------------------------------------------------------------------
__global__ void k_dinv() {
    int i = blockIdx.x * blockDim.x + threadIdx.x;
    if (i < NN) {
        float d = g_deg[i];
        g_dinv[i] = (d > 0.0f) ? rsqrtf(d) : 0.0f;
    }
}

// ---------------------------------------------------------------------------
// K3: exclusive scan of count -> off, cur  (single block, 1024 threads)
// ---------------------------------------------------------------------------
__global__ void k_scan() {
    __shared__ int ssum[SCAN_T];
    const int t = threadIdx.x;
    const int base = t * CH;

    int sum = 0;
    #pragma unroll 4
    for (int i = 0; i < CH; i++) {
        int idx = base + i;
        if (idx < NN) sum += g_count[idx];
    }
    ssum[t] = sum;
    __syncthreads();

    // Hillis-Steele inclusive scan over 1024 partials
    for (int off = 1; off < SCAN_T; off <<= 1) {
        int v = (t >= off) ? ssum[t - off] : 0;
        __syncthreads();
        ssum[t] += v;
        __syncthreads();
    }
    int run = (t == 0) ? 0 : ssum[t - 1];

    for (int i = 0; i < CH; i++) {
        int idx = base + i;
        if (idx < NN) {
            g_off[idx] = run;
            g_cur[idx] = run;
            run += g_count[idx];
        }
    }
    if (t == SCAN_T - 1) g_off[NN] = run;
}

// ---------------------------------------------------------------------------
// K4: CSR fill — csr[pos] = (src, dinv[s]*w*dinv[d]) for edges grouped by dst
// ---------------------------------------------------------------------------
__global__ void k_fill(const int* __restrict__ src,
                       const int* __restrict__ dst,
                       const float* __restrict__ w, int E) {
    int e = blockIdx.x * blockDim.x + threadIdx.x;
    if (e >= E) return;
    unsigned s = (unsigned)src[e];
    unsigned d = (unsigned)dst[e];
    if (s >= NN || d >= NN) return;
    int pos = atomicAdd(&g_cur[d], 1);
    g_csr_src[pos]  = (int)s;
    g_csr_norm[pos] = g_dinv[s] * w[e] * g_dinv[d];
}

// ---------------------------------------------------------------------------
// K5: h = x @ W ; out = b + dinv^2 * h   (self-loop term + bias, full init)
// ---------------------------------------------------------------------------
__global__ void k_gemm(const float* __restrict__ x,
                       const float* __restrict__ W,
                       const float* __restrict__ b,
                       float* __restrict__ out) {
    extern __shared__ char smem[];
    float4* Ws = (float4*)smem;                 // [128][32] float4  = 64KB
    float*  Xs = (float*)(smem + 64 * 1024);    // [32][128] float   = 16KB

    const int t = threadIdx.x;
    const int c = t & 31;
    const int r = t >> 5;

    const float4* W4 = (const float4*)W;
    #pragma unroll
    for (int i = 0; i < 16; i++) Ws[t + i * 256] = W4[t + i * 256];

    const float4 b4 = ((const float4*)b)[c];

    for (int tile = blockIdx.x; tile < NTILES; tile += gridDim.x) {
        const int row0 = tile * 32;

        __syncthreads();
        const float4* X4 = (const float4*)(x + (size_t)row0 * DD);
        float4* Xs4 = (float4*)Xs;
        #pragma unroll
        for (int i = 0; i < 4; i++) Xs4[t + i * 256] = X4[t + i * 256];
        __syncthreads();

        float4 acc0 = make_float4(0.f, 0.f, 0.f, 0.f);
        float4 acc1 = make_float4(0.f, 0.f, 0.f, 0.f);
        float4 acc2 = make_float4(0.f, 0.f, 0.f, 0.f);
        float4 acc3 = make_float4(0.f, 0.f, 0.f, 0.f);

        #pragma unroll 8
        for (int k = 0; k < DD; k++) {
            const float4 w4 = Ws[k * 32 + c];
            const float x0 = Xs[(r     ) * DD + k];
            const float x1 = Xs[(r +  8) * DD + k];
            const float x2 = Xs[(r + 16) * DD + k];
            const float x3 = Xs[(r + 24) * DD + k];
            acc0.x += x0 * w4.x; acc0.y += x0 * w4.y; acc0.z += x0 * w4.z; acc0.w += x0 * w4.w;
            acc1.x += x1 * w4.x; acc1.y += x1 * w4.y; acc1.z += x1 * w4.z; acc1.w += x1 * w4.w;
            acc2.x += x2 * w4.x; acc2.y += x2 * w4.y; acc2.z += x2 * w4.z; acc2.w += x2 * w4.w;
            acc3.x += x3 * w4.x; acc3.y += x3 * w4.y; acc3.z += x3 * w4.z; acc3.w += x3 * w4.w;
        }

        float4 accs[4] = {acc0, acc1, acc2, acc3};
        #pragma unroll
        for (int m = 0; m < 4; m++) {
            const int row = row0 + r + 8 * m;
            const float di = g_dinv[row];
            const float n2 = di * di;
            ((float4*)(g_h + (size_t)row * DD))[c] = accs[m];
            float4 o;
            o.x = b4.x + n2 * accs[m].x;
            o.y = b4.y + n2 * accs[m].y;
            o.z = b4.z + n2 * accs[m].z;
            o.w = b4.w + n2 * accs[m].w;
            ((float4*)(out + (size_t)row * DD))[c] = o;
        }
    }
}

// ---------------------------------------------------------------------------
// K6: aggregate — one warp per node, registers accumulate, single RMW store.
// No atomics.
// ---------------------------------------------------------------------------
__global__ void k_agg(float* __restrict__ out) {
    const int node = (blockIdx.x * blockDim.x + threadIdx.x) >> 5;
    const int lane = threadIdx.x & 31;
    if (node >= NN) return;

    const int beg = g_off[node];
    const int end = g_off[node + 1];

    float4 acc = make_float4(0.f, 0.f, 0.f, 0.f);
    #pragma unroll 4
    for (int e = beg; e < end; e++) {
        const int   s  = g_csr_src[e];
        const float nm = g_csr_norm[e];
        const float4 v = ((const float4*)(g_h + (size_t)s * DD))[lane];
        acc.x += nm * v.x;
        acc.y += nm * v.y;
        acc.z += nm * v.z;
        acc.w += nm * v.w;
    }

    float4* o = (float4*)(out + (size_t)node * DD) + lane;
    float4 cur = *o;
    cur.x += acc.x; cur.y += acc.y; cur.z += acc.z; cur.w += acc.w;
    *o = cur;
}

// ---------------------------------------------------------------------------
extern "C" void kernel_launch(void* const* d_in, const int* in_sizes, int n_in,
                              void* d_out, int out_size) {
    // Bind inputs by unique element count (robust to metadata ordering)
    const float* x  = nullptr;
    const int*   ei = nullptr;
    const float* ew = nullptr;
    const float* W  = nullptr;
    const float* b  = nullptr;
    int E = 0;
    for (int i = 0; i < n_in; i++) {
        const int sz = in_sizes[i];
        if      (sz == NN * DD)   x  = (const float*)d_in[i];
        else if (sz == 2 * EE)    ei = (const int*)d_in[i];
        else if (sz == EE)        { ew = (const float*)d_in[i]; E = sz; }
        else if (sz == DD * DD)   W  = (const float*)d_in[i];
        else if (sz == DD)        b  = (const float*)d_in[i];
    }
    if (!x || !ei || !ew || !W || !b) return;

    float* out = (float*)d_out;
    const int* src = ei;
    const int* dst = ei + E;

    k_init<<<(NN + 255) / 256, 256>>>();
    k_deg_count<<<(E + 255) / 256, 256>>>(dst, ew, E);
    k_dinv<<<(NN + 255) / 256, 256>>>();
    k_scan<<<1, SCAN_T>>>();
    k_fill<<<(E + 255) / 256, 256>>>(src, dst, ew, E);

    static bool attr_set = false;
    if (!attr_set) {
        cudaFuncSetAttribute(k_gemm, cudaFuncAttributeMaxDynamicSharedMemorySize,
                             80 * 1024);
        attr_set = true;
    }
    k_gemm<<<296, 256, 80 * 1024>>>(x, W, b, out);

    k_agg<<<(NN * 32 + 255) / 256, 256>>>(out);
}

// round 5
// speedup vs baseline: 1.9358x; 1.5126x over previous
#include <cuda_runtime.h>
#include <cstdint>

#define NN  100000
#define DD  128
#define EE  3200000
#define NTILES (NN / 32)     // 3125, exact
#define SCAN_B 98            // ceil(100000/1024)

// Scratch (static device arrays; no allocs allowed)
__device__ float g_deg[NN];
__device__ float g_dinv[NN];
__device__ float g_h[(size_t)NN * DD];        // 51.2 MB
__device__ int   g_count[NN];
__device__ int   g_off[NN + 1];
__device__ int   g_cur[NN];
__device__ int   g_bsum[SCAN_B];
__device__ int   g_bpref[SCAN_B];
__device__ int   g_csr_src[EE];               // 12.8 MB
__device__ float g_csr_norm[EE];              // 12.8 MB

// ---------------------------------------------------------------------------
// K0: deg[i] = 1.0 (self-loop folded in), count[i] = 0
// ---------------------------------------------------------------------------
__global__ void k_init() {
    int i = blockIdx.x * blockDim.x + threadIdx.x;
    if (i < NN) { g_deg[i] = 1.0f; g_count[i] = 0; }
}

// ---------------------------------------------------------------------------
// K1: deg[dst] += w ; count[dst] += 1
// ---------------------------------------------------------------------------
__global__ void k_deg_count(const int* __restrict__ dst,
                            const float* __restrict__ w, int E) {
    int e = blockIdx.x * blockDim.x + threadIdx.x;
    if (e < E) {
        unsigned d = (unsigned)dst[e];
        if (d < NN) {
            atomicAdd(&g_deg[d], w[e]);
            atomicAdd(&g_count[d], 1);
        }
    }
}

// ---------------------------------------------------------------------------
// K2: dinv = rsqrt(deg)
// ---------------------------------------------------------------------------
__global__ void k_dinv() {
    int i = blockIdx.x * blockDim.x + threadIdx.x;
    if (i < NN) {
        float d = g_deg[i];
        g_dinv[i] = (d > 0.0f) ? rsqrtf(d) : 0.0f;
    }
}

// ---------------------------------------------------------------------------
// Scan stage 1: per-block sums (98 blocks x 1024, coalesced)
// ---------------------------------------------------------------------------
__global__ void k_scan1() {
    __shared__ int swarp[32];
    const int t = threadIdx.x;
    const int idx = blockIdx.x * 1024 + t;
    int v = (idx < NN) ? g_count[idx] : 0;

    #pragma unroll
    for (int o = 16; o > 0; o >>= 1) v += __shfl_down_sync(~0u, v, o);
    if ((t & 31) == 0) swarp[t >> 5] = v;
    __syncthreads();
    if (t < 32) {
        int s = swarp[t];
        #pragma unroll
        for (int o = 16; o > 0; o >>= 1) s += __shfl_down_sync(~0u, s, o);
        if (t == 0) g_bsum[blockIdx.x] = s;
    }
}

// ---------------------------------------------------------------------------
// Scan stage 2: scan the 98 block sums (1 block x 128)
// ---------------------------------------------------------------------------
__global__ void k_scan2() {
    __shared__ int s[128];
    const int t = threadIdx.x;
    s[t] = (t < SCAN_B) ? g_bsum[t] : 0;
    __syncthreads();
    #pragma unroll
    for (int o = 1; o < 128; o <<= 1) {
        int v = (t >= o) ? s[t - o] : 0;
        __syncthreads();
        s[t] += v;
        __syncthreads();
    }
    if (t < SCAN_B) g_bpref[t] = (t == 0) ? 0 : s[t - 1];
    if (t == 127) g_off[NN] = s[127];
}

// ---------------------------------------------------------------------------
// Scan stage 3: per-element exclusive offsets (98 blocks x 1024)
// ---------------------------------------------------------------------------
__global__ void k_scan3() {
    __shared__ int swarp[33];
    const int t = threadIdx.x;
    const int lane = t & 31;
    const int wid = t >> 5;
    const int idx = blockIdx.x * 1024 + t;
    const int val = (idx < NN) ? g_count[idx] : 0;

    // warp inclusive scan
    int v = val;
    #pragma unroll
    for (int o = 1; o < 32; o <<= 1) {
        int n = __shfl_up_sync(~0u, v, o);
        if (lane >= o) v += n;
    }
    if (lane == 31) swarp[wid] = v;
    __syncthreads();
    if (t < 32) {
        int s = swarp[t];
        #pragma unroll
        for (int o = 1; o < 32; o <<= 1) {
            int n = __shfl_up_sync(~0u, s, o);
            if (t >= o) s += n;
        }
        swarp[t + 1] = s;   // inclusive -> use [wid] as exclusive below
        if (t == 0) swarp[0] = 0;
    }
    __syncthreads();

    if (idx < NN) {
        int excl = g_bpref[blockIdx.x] + swarp[wid] + (v - val);
        g_off[idx] = excl;
        g_cur[idx] = excl;
    }
}

// ---------------------------------------------------------------------------
// K4: CSR fill — csr[pos] = (src, dinv[s]*w*dinv[d]) for edges grouped by dst
// ---------------------------------------------------------------------------
__global__ void k_fill(const int* __restrict__ src,
                       const int* __restrict__ dst,
                       const float* __restrict__ w, int E) {
    int e = blockIdx.x * blockDim.x + threadIdx.x;
    if (e >= E) return;
    unsigned s = (unsigned)src[e];
    unsigned d = (unsigned)dst[e];
    if (s >= NN || d >= NN) return;
    int pos = atomicAdd(&g_cur[d], 1);
    g_csr_src[pos]  = (int)s;
    g_csr_norm[pos] = g_dinv[s] * w[e] * g_dinv[d];
}

// ---------------------------------------------------------------------------
// K5: h = x @ W ; out = b + dinv^2 * h   (self-loop term + bias, full init)
// ---------------------------------------------------------------------------
__global__ void k_gemm(const float* __restrict__ x,
                       const float* __restrict__ W,
                       const float* __restrict__ b,
                       float* __restrict__ out) {
    extern __shared__ char smem[];
    float4* Ws = (float4*)smem;                 // [128][32] float4  = 64KB
    float*  Xs = (float*)(smem + 64 * 1024);    // [32][128] float   = 16KB

    const int t = threadIdx.x;
    const int c = t & 31;
    const int r = t >> 5;

    const float4* W4 = (const float4*)W;
    #pragma unroll
    for (int i = 0; i < 16; i++) Ws[t + i * 256] = W4[t + i * 256];

    const float4 b4 = ((const float4*)b)[c];

    for (int tile = blockIdx.x; tile < NTILES; tile += gridDim.x) {
        const int row0 = tile * 32;

        __syncthreads();
        const float4* X4 = (const float4*)(x + (size_t)row0 * DD);
        float4* Xs4 = (float4*)Xs;
        #pragma unroll
        for (int i = 0; i < 4; i++) Xs4[t + i * 256] = X4[t + i * 256];
        __syncthreads();

        float4 acc0 = make_float4(0.f, 0.f, 0.f, 0.f);
        float4 acc1 = make_float4(0.f, 0.f, 0.f, 0.f);
        float4 acc2 = make_float4(0.f, 0.f, 0.f, 0.f);
        float4 acc3 = make_float4(0.f, 0.f, 0.f, 0.f);

        #pragma unroll 8
        for (int k = 0; k < DD; k++) {
            const float4 w4 = Ws[k * 32 + c];
            const float x0 = Xs[(r     ) * DD + k];
            const float x1 = Xs[(r +  8) * DD + k];
            const float x2 = Xs[(r + 16) * DD + k];
            const float x3 = Xs[(r + 24) * DD + k];
            acc0.x += x0 * w4.x; acc0.y += x0 * w4.y; acc0.z += x0 * w4.z; acc0.w += x0 * w4.w;
            acc1.x += x1 * w4.x; acc1.y += x1 * w4.y; acc1.z += x1 * w4.z; acc1.w += x1 * w4.w;
            acc2.x += x2 * w4.x; acc2.y += x2 * w4.y; acc2.z += x2 * w4.z; acc2.w += x2 * w4.w;
            acc3.x += x3 * w4.x; acc3.y += x3 * w4.y; acc3.z += x3 * w4.z; acc3.w += x3 * w4.w;
        }

        float4 accs[4] = {acc0, acc1, acc2, acc3};
        #pragma unroll
        for (int m = 0; m < 4; m++) {
            const int row = row0 + r + 8 * m;
            const float di = g_dinv[row];
            const float n2 = di * di;
            ((float4*)(g_h + (size_t)row * DD))[c] = accs[m];
            float4 o;
            o.x = b4.x + n2 * accs[m].x;
            o.y = b4.y + n2 * accs[m].y;
            o.z = b4.z + n2 * accs[m].z;
            o.w = b4.w + n2 * accs[m].w;
            ((float4*)(out + (size_t)row * DD))[c] = o;
        }
    }
}

// ---------------------------------------------------------------------------
// K6: aggregate — one warp per node, registers accumulate, single RMW store.
// ---------------------------------------------------------------------------
__global__ void k_agg(float* __restrict__ out) {
    const int node = (blockIdx.x * blockDim.x + threadIdx.x) >> 5;
    const int lane = threadIdx.x & 31;
    if (node >= NN) return;

    const int beg = g_off[node];
    const int end = g_off[node + 1];

    float4 acc = make_float4(0.f, 0.f, 0.f, 0.f);
    #pragma unroll 4
    for (int e = beg; e < end; e++) {
        const int   s  = g_csr_src[e];
        const float nm = g_csr_norm[e];
        const float4 v = ((const float4*)(g_h + (size_t)s * DD))[lane];
        acc.x += nm * v.x;
        acc.y += nm * v.y;
        acc.z += nm * v.z;
        acc.w += nm * v.w;
    }

    float4* o = (float4*)(out + (size_t)node * DD) + lane;
    float4 cur = *o;
    cur.x += acc.x; cur.y += acc.y; cur.z += acc.z; cur.w += acc.w;
    *o = cur;
}

// ---------------------------------------------------------------------------
extern "C" void kernel_launch(void* const* d_in, const int* in_sizes, int n_in,
                              void* d_out, int out_size) {
    // Bind inputs by unique element count (robust to metadata ordering)
    const float* x  = nullptr;
    const int*   ei = nullptr;
    const float* ew = nullptr;
    const float* W  = nullptr;
    const float* b  = nullptr;
    int E = 0;
    for (int i = 0; i < n_in; i++) {
        const int sz = in_sizes[i];
        if      (sz == NN * DD)   x  = (const float*)d_in[i];
        else if (sz == 2 * EE)    ei = (const int*)d_in[i];
        else if (sz == EE)        { ew = (const float*)d_in[i]; E = sz; }
        else if (sz == DD * DD)   W  = (const float*)d_in[i];
        else if (sz == DD)        b  = (const float*)d_in[i];
    }
    if (!x || !ei || !ew || !W || !b) return;

    float* out = (float*)d_out;
    const int* src = ei;
    const int* dst = ei + E;

    k_init<<<(NN + 255) / 256, 256>>>();
    k_deg_count<<<(E + 255) / 256, 256>>>(dst, ew, E);
    k_dinv<<<(NN + 255) / 256, 256>>>();
    k_scan1<<<SCAN_B, 1024>>>();
    k_scan2<<<1, 128>>>();
    k_scan3<<<SCAN_B, 1024>>>();
    k_fill<<<(E + 255) / 256, 256>>>(src, dst, ew, E);

    static bool attr_set = false;
    if (!attr_set) {
        cudaFuncSetAttribute(k_gemm, cudaFuncAttributeMaxDynamicSharedMemorySize,
                             80 * 1024);
        attr_set = true;
    }
    k_gemm<<<296, 256, 80 * 1024>>>(x, W, b, out);

    k_agg<<<(NN * 32 + 255) / 256, 256>>>(out);
}

// round 6
// speedup vs baseline: 2.2813x; 1.1785x over previous
#include <cuda_runtime.h>
#include <cuda_fp16.h>
#include <cstdint>

#define NN  100000
#define DD  128
#define EE  3200000
#define NTILES (NN / 32)     // 3125, exact
#define SCAN_B 98            // ceil(100000/1024)

// Scratch (static device arrays; no allocs allowed)
__device__ float  g_deg[NN];
__device__ float  g_dinv[NN];
__device__ __half g_h16[(size_t)NN * DD];     // 25.6 MB (gather payload)
__device__ int    g_count[NN];
__device__ int    g_off[NN + 1];
__device__ int    g_cur[NN];
__device__ int    g_bsum[SCAN_B];
__device__ int    g_bpref[SCAN_B];
__device__ int2   g_csr[EE];                  // (src, norm bits) 25.6 MB

// ---------------------------------------------------------------------------
// K0: deg[i] = 1.0 (self-loop folded in), count[i] = 0
// ---------------------------------------------------------------------------
__global__ void k_init() {
    int i = blockIdx.x * blockDim.x + threadIdx.x;
    if (i < NN) { g_deg[i] = 1.0f; g_count[i] = 0; }
}

// ---------------------------------------------------------------------------
// K1: deg[dst] += w ; count[dst] += 1   (4 edges per thread, vector loads)
// ---------------------------------------------------------------------------
__global__ void k_deg_count(const int* __restrict__ dst,
                            const float* __restrict__ w, int E4) {
    int i = blockIdx.x * blockDim.x + threadIdx.x;
    if (i >= E4) return;
    const int4   d4 = ((const int4*)dst)[i];
    const float4 w4 = ((const float4*)w)[i];
    #pragma unroll
    for (int j = 0; j < 4; j++) {
        unsigned d = (unsigned)(&d4.x)[j];
        if (d < NN) {
            atomicAdd(&g_deg[d], (&w4.x)[j]);
            atomicAdd(&g_count[d], 1);
        }
    }
}

// ---------------------------------------------------------------------------
// Scan stage 1: per-block sums + dinv (98 blocks x 1024)
// ---------------------------------------------------------------------------
__global__ void k_scan1() {
    __shared__ int swarp[32];
    const int t = threadIdx.x;
    const int idx = blockIdx.x * 1024 + t;
    int v = 0;
    if (idx < NN) {
        v = g_count[idx];
        float d = g_deg[idx];
        g_dinv[idx] = (d > 0.0f) ? rsqrtf(d) : 0.0f;
    }
    int s = v;
    #pragma unroll
    for (int o = 16; o > 0; o >>= 1) s += __shfl_down_sync(~0u, s, o);
    if ((t & 31) == 0) swarp[t >> 5] = s;
    __syncthreads();
    if (t < 32) {
        int ss = swarp[t];
        #pragma unroll
        for (int o = 16; o > 0; o >>= 1) ss += __shfl_down_sync(~0u, ss, o);
        if (t == 0) g_bsum[blockIdx.x] = ss;
    }
}

// ---------------------------------------------------------------------------
// Scan stage 2: scan the 98 block sums (1 block x 128)
// ---------------------------------------------------------------------------
__global__ void k_scan2() {
    __shared__ int s[128];
    const int t = threadIdx.x;
    s[t] = (t < SCAN_B) ? g_bsum[t] : 0;
    __syncthreads();
    #pragma unroll
    for (int o = 1; o < 128; o <<= 1) {
        int v = (t >= o) ? s[t - o] : 0;
        __syncthreads();
        s[t] += v;
        __syncthreads();
    }
    if (t < SCAN_B) g_bpref[t] = (t == 0) ? 0 : s[t - 1];
    if (t == 127) g_off[NN] = s[127];
}

// ---------------------------------------------------------------------------
// Scan stage 3: per-element exclusive offsets (98 blocks x 1024)
// ---------------------------------------------------------------------------
__global__ void k_scan3() {
    __shared__ int swarp[33];
    const int t = threadIdx.x;
    const int lane = t & 31;
    const int wid = t >> 5;
    const int idx = blockIdx.x * 1024 + t;
    const int val = (idx < NN) ? g_count[idx] : 0;

    int v = val;
    #pragma unroll
    for (int o = 1; o < 32; o <<= 1) {
        int n = __shfl_up_sync(~0u, v, o);
        if (lane >= o) v += n;
    }
    if (lane == 31) swarp[wid] = v;
    __syncthreads();
    if (t < 32) {
        int s = swarp[t];
        #pragma unroll
        for (int o = 1; o < 32; o <<= 1) {
            int n = __shfl_up_sync(~0u, s, o);
            if (t >= o) s += n;
        }
        swarp[t + 1] = s;
        if (t == 0) swarp[0] = 0;
    }
    __syncthreads();

    if (idx < NN) {
        int excl = g_bpref[blockIdx.x] + swarp[wid] + (v - val);
        g_off[idx] = excl;
        g_cur[idx] = excl;
    }
}

// ---------------------------------------------------------------------------
// K4: CSR fill — g_csr[pos] = (src, w*dinv[src]); dinv[dst] folded into agg.
// 4 edges per thread.
// ---------------------------------------------------------------------------
__global__ void k_fill(const int* __restrict__ src,
                       const int* __restrict__ dst,
                       const float* __restrict__ w, int E4) {
    int i = blockIdx.x * blockDim.x + threadIdx.x;
    if (i >= E4) return;
    const int4   s4 = ((const int4*)src)[i];
    const int4   d4 = ((const int4*)dst)[i];
    const float4 w4 = ((const float4*)w)[i];
    #pragma unroll
    for (int j = 0; j < 4; j++) {
        unsigned s = (unsigned)(&s4.x)[j];
        unsigned d = (unsigned)(&d4.x)[j];
        if (s >= NN || d >= NN) continue;
        int pos = atomicAdd(&g_cur[d], 1);
        float nm = (&w4.x)[j] * g_dinv[s];
        g_csr[pos] = make_int2((int)s, __float_as_int(nm));
    }
}

// ---------------------------------------------------------------------------
// K5: h = x @ W ; out = b + dinv^2 * h (fp32 exact); h stored fp16 for agg.
// ---------------------------------------------------------------------------
__global__ void k_gemm(const float* __restrict__ x,
                       const float* __restrict__ W,
                       const float* __restrict__ b,
                       float* __restrict__ out) {
    extern __shared__ char smem[];
    float4* Ws = (float4*)smem;                 // [128][32] float4  = 64KB
    float*  Xs = (float*)(smem + 64 * 1024);    // [32][128] float   = 16KB

    const int t = threadIdx.x;
    const int c = t & 31;
    const int r = t >> 5;

    const float4* W4 = (const float4*)W;
    #pragma unroll
    for (int i = 0; i < 16; i++) Ws[t + i * 256] = W4[t + i * 256];

    const float4 b4 = ((const float4*)b)[c];

    for (int tile = blockIdx.x; tile < NTILES; tile += gridDim.x) {
        const int row0 = tile * 32;

        __syncthreads();
        const float4* X4 = (const float4*)(x + (size_t)row0 * DD);
        float4* Xs4 = (float4*)Xs;
        #pragma unroll
        for (int i = 0; i < 4; i++) Xs4[t + i * 256] = X4[t + i * 256];
        __syncthreads();

        float4 acc0 = make_float4(0.f, 0.f, 0.f, 0.f);
        float4 acc1 = make_float4(0.f, 0.f, 0.f, 0.f);
        float4 acc2 = make_float4(0.f, 0.f, 0.f, 0.f);
        float4 acc3 = make_float4(0.f, 0.f, 0.f, 0.f);

        #pragma unroll 8
        for (int k = 0; k < DD; k++) {
            const float4 w4 = Ws[k * 32 + c];
            const float x0 = Xs[(r     ) * DD + k];
            const float x1 = Xs[(r +  8) * DD + k];
            const float x2 = Xs[(r + 16) * DD + k];
            const float x3 = Xs[(r + 24) * DD + k];
            acc0.x += x0 * w4.x; acc0.y += x0 * w4.y; acc0.z += x0 * w4.z; acc0.w += x0 * w4.w;
            acc1.x += x1 * w4.x; acc1.y += x1 * w4.y; acc1.z += x1 * w4.z; acc1.w += x1 * w4.w;
            acc2.x += x2 * w4.x; acc2.y += x2 * w4.y; acc2.z += x2 * w4.z; acc2.w += x2 * w4.w;
            acc3.x += x3 * w4.x; acc3.y += x3 * w4.y; acc3.z += x3 * w4.z; acc3.w += x3 * w4.w;
        }

        float4 accs[4] = {acc0, acc1, acc2, acc3};
        #pragma unroll
        for (int m = 0; m < 4; m++) {
            const int row = row0 + r + 8 * m;
            const float di = g_dinv[row];
            const float n2 = di * di;
            // fp16 h for the gather path
            __half2 h0 = __float22half2_rn(make_float2(accs[m].x, accs[m].y));
            __half2 h1 = __float22half2_rn(make_float2(accs[m].z, accs[m].w));
            uint2 hv;
            hv.x = *(unsigned*)&h0;
            hv.y = *(unsigned*)&h1;
            ((uint2*)(g_h16 + (size_t)row * DD))[c] = hv;
            // exact fp32 self-loop + bias
            float4 o;
            o.x = b4.x + n2 * accs[m].x;
            o.y = b4.y + n2 * accs[m].y;
            o.z = b4.z + n2 * accs[m].z;
            o.w = b4.w + n2 * accs[m].w;
            ((float4*)(out + (size_t)row * DD))[c] = o;
        }
    }
}

// ---------------------------------------------------------------------------
// K6: aggregate — one warp per node; fp16 gathers, fp32 accumulate;
// multiply by dinv[node] once; single RMW store. No atomics.
// ---------------------------------------------------------------------------
__global__ void k_agg(float* __restrict__ out) {
    const int node = (blockIdx.x * blockDim.x + threadIdx.x) >> 5;
    const int lane = threadIdx.x & 31;
    if (node >= NN) return;

    const int beg = g_off[node];
    const int end = g_off[node + 1];

    float4 acc = make_float4(0.f, 0.f, 0.f, 0.f);
    #pragma unroll 4
    for (int e = beg; e < end; e++) {
        const int2  p  = g_csr[e];
        const float nm = __int_as_float(p.y);
        const uint2 hv = ((const uint2*)(g_h16 + (size_t)p.x * DD))[lane];
        const float2 v0 = __half22float2(*(const __half2*)&hv.x);
        const float2 v1 = __half22float2(*(const __half2*)&hv.y);
        acc.x += nm * v0.x;
        acc.y += nm * v0.y;
        acc.z += nm * v1.x;
        acc.w += nm * v1.y;
    }

    const float dd = g_dinv[node];
    float4* o = (float4*)(out + (size_t)node * DD) + lane;
    float4 cur = *o;
    cur.x += dd * acc.x; cur.y += dd * acc.y;
    cur.z += dd * acc.z; cur.w += dd * acc.w;
    *o = cur;
}

// ---------------------------------------------------------------------------
extern "C" void kernel_launch(void* const* d_in, const int* in_sizes, int n_in,
                              void* d_out, int out_size) {
    // Bind inputs by unique element count (robust to metadata ordering)
    const float* x  = nullptr;
    const int*   ei = nullptr;
    const float* ew = nullptr;
    const float* W  = nullptr;
    const float* b  = nullptr;
    int E = 0;
    for (int i = 0; i < n_in; i++) {
        const int sz = in_sizes[i];
        if      (sz == NN * DD)   x  = (const float*)d_in[i];
        else if (sz == 2 * EE)    ei = (const int*)d_in[i];
        else if (sz == EE)        { ew = (const float*)d_in[i]; E = sz; }
        else if (sz == DD * DD)   W  = (const float*)d_in[i];
        else if (sz == DD)        b  = (const float*)d_in[i];
    }
    if (!x || !ei || !ew || !W || !b) return;

    float* out = (float*)d_out;
    const int* src = ei;
    const int* dst = ei + E;
    const int E4 = E / 4;   // E = 3,200,000 divisible by 4

    k_init<<<(NN + 255) / 256, 256>>>();
    k_deg_count<<<(E4 + 255) / 256, 256>>>(dst, ew, E4);
    k_scan1<<<SCAN_B, 1024>>>();
    k_scan2<<<1, 128>>>();
    k_scan3<<<SCAN_B, 1024>>>();
    k_fill<<<(E4 + 255) / 256, 256>>>(src, dst, ew, E4);

    static bool attr_set = false;
    if (!attr_set) {
        cudaFuncSetAttribute(k_gemm, cudaFuncAttributeMaxDynamicSharedMemorySize,
                             80 * 1024);
        attr_set = true;
    }
    k_gemm<<<296, 256, 80 * 1024>>>(x, W, b, out);

    k_agg<<<(NN * 32 + 255) / 256, 256>>>(out);
}

// round 7
// speedup vs baseline: 2.8891x; 1.2664x over previous
#include <cuda_runtime.h>
#include <cuda_fp16.h>
#include <cstdint>

#define NN  100000
#define DD  128
#define EE  3200000
#define NTILES (NN / 32)     // 3125, exact
#define SCAN_B 98            // ceil(100000/1024)

// Scratch (static device arrays; no allocs allowed)
__device__ float  g_deg[NN];
__device__ float  g_dinv[NN];
__device__ __half g_h16[(size_t)NN * DD];     // 25.6 MB (gather payload)
__device__ int    g_count[NN];
__device__ int    g_off[NN + 1];
__device__ int    g_cur[NN];
__device__ int    g_bsum[SCAN_B];
__device__ int    g_bpref[SCAN_B];
__device__ int2   g_csr[EE];                  // (src, w*dinv[src]) 25.6 MB

// ---------------------------------------------------------------------------
__global__ void k_init() {
    int i = blockIdx.x * blockDim.x + threadIdx.x;
    if (i < NN) { g_deg[i] = 1.0f; g_count[i] = 0; }
}

// ---------------------------------------------------------------------------
// deg[dst] += w ; count[dst] += 1   (4 edges per thread, vector loads)
// ---------------------------------------------------------------------------
__global__ void k_deg_count(const int* __restrict__ dst,
                            const float* __restrict__ w, int E4) {
    int i = blockIdx.x * blockDim.x + threadIdx.x;
    if (i >= E4) return;
    const int4   d4 = ((const int4*)dst)[i];
    const float4 w4 = ((const float4*)w)[i];
    #pragma unroll
    for (int j = 0; j < 4; j++) {
        unsigned d = (unsigned)(&d4.x)[j];
        if (d < NN) {
            atomicAdd(&g_deg[d], (&w4.x)[j]);
            atomicAdd(&g_count[d], 1);
        }
    }
}

// ---------------------------------------------------------------------------
// Scan stage 1: per-block sums + dinv (98 blocks x 1024)
// ---------------------------------------------------------------------------
__global__ void k_scan1() {
    __shared__ int swarp[32];
    const int t = threadIdx.x;
    const int idx = blockIdx.x * 1024 + t;
    int v = 0;
    if (idx < NN) {
        v = g_count[idx];
        float d = g_deg[idx];
        g_dinv[idx] = (d > 0.0f) ? rsqrtf(d) : 0.0f;
    }
    int s = v;
    #pragma unroll
    for (int o = 16; o > 0; o >>= 1) s += __shfl_down_sync(~0u, s, o);
    if ((t & 31) == 0) swarp[t >> 5] = s;
    __syncthreads();
    if (t < 32) {
        int ss = swarp[t];
        #pragma unroll
        for (int o = 16; o > 0; o >>= 1) ss += __shfl_down_sync(~0u, ss, o);
        if (t == 0) g_bsum[blockIdx.x] = ss;
    }
}

// ---------------------------------------------------------------------------
__global__ void k_scan2() {
    __shared__ int s[128];
    const int t = threadIdx.x;
    s[t] = (t < SCAN_B) ? g_bsum[t] : 0;
    __syncthreads();
    #pragma unroll
    for (int o = 1; o < 128; o <<= 1) {
        int v = (t >= o) ? s[t - o] : 0;
        __syncthreads();
        s[t] += v;
        __syncthreads();
    }
    if (t < SCAN_B) g_bpref[t] = (t == 0) ? 0 : s[t - 1];
    if (t == 127) g_off[NN] = s[127];
}

// ---------------------------------------------------------------------------
__global__ void k_scan3() {
    __shared__ int swarp[33];
    const int t = threadIdx.x;
    const int lane = t & 31;
    const int wid = t >> 5;
    const int idx = blockIdx.x * 1024 + t;
    const int val = (idx < NN) ? g_count[idx] : 0;

    int v = val;
    #pragma unroll
    for (int o = 1; o < 32; o <<= 1) {
        int n = __shfl_up_sync(~0u, v, o);
        if (lane >= o) v += n;
    }
    if (lane == 31) swarp[wid] = v;
    __syncthreads();
    if (t < 32) {
        int s = swarp[t];
        #pragma unroll
        for (int o = 1; o < 32; o <<= 1) {
            int n = __shfl_up_sync(~0u, s, o);
            if (t >= o) s += n;
        }
        swarp[t + 1] = s;
        if (t == 0) swarp[0] = 0;
    }
    __syncthreads();

    if (idx < NN) {
        int excl = g_bpref[blockIdx.x] + swarp[wid] + (v - val);
        g_off[idx] = excl;
        g_cur[idx] = excl;
    }
}

// ---------------------------------------------------------------------------
// CSR fill — g_csr[pos] = (src, w*dinv[src]); dinv[dst] folded into agg.
// ---------------------------------------------------------------------------
__global__ void k_fill(const int* __restrict__ src,
                       const int* __restrict__ dst,
                       const float* __restrict__ w, int E4) {
    int i = blockIdx.x * blockDim.x + threadIdx.x;
    if (i >= E4) return;
    const int4   s4 = ((const int4*)src)[i];
    const int4   d4 = ((const int4*)dst)[i];
    const float4 w4 = ((const float4*)w)[i];
    #pragma unroll
    for (int j = 0; j < 4; j++) {
        unsigned s = (unsigned)(&s4.x)[j];
        unsigned d = (unsigned)(&d4.x)[j];
        if (s >= NN || d >= NN) continue;
        int pos = atomicAdd(&g_cur[d], 1);
        float nm = (&w4.x)[j] * g_dinv[s];
        g_csr[pos] = make_int2((int)s, __float_as_int(nm));
    }
}

// ---------------------------------------------------------------------------
// GEMM: h16 = fp16(x @ W). No other outputs — fully independent of edge chain.
// ---------------------------------------------------------------------------
__global__ void k_gemm(const float* __restrict__ x,
                       const float* __restrict__ W) {
    extern __shared__ char smem[];
    float4* Ws = (float4*)smem;                 // [128][32] float4  = 64KB
    float*  Xs = (float*)(smem + 64 * 1024);    // [32][128] float   = 16KB

    const int t = threadIdx.x;
    const int c = t & 31;
    const int r = t >> 5;

    const float4* W4 = (const float4*)W;
    #pragma unroll
    for (int i = 0; i < 16; i++) Ws[t + i * 256] = W4[t + i * 256];

    for (int tile = blockIdx.x; tile < NTILES; tile += gridDim.x) {
        const int row0 = tile * 32;

        __syncthreads();
        const float4* X4 = (const float4*)(x + (size_t)row0 * DD);
        float4* Xs4 = (float4*)Xs;
        #pragma unroll
        for (int i = 0; i < 4; i++) Xs4[t + i * 256] = X4[t + i * 256];
        __syncthreads();

        float4 acc0 = make_float4(0.f, 0.f, 0.f, 0.f);
        float4 acc1 = make_float4(0.f, 0.f, 0.f, 0.f);
        float4 acc2 = make_float4(0.f, 0.f, 0.f, 0.f);
        float4 acc3 = make_float4(0.f, 0.f, 0.f, 0.f);

        #pragma unroll 8
        for (int k = 0; k < DD; k++) {
            const float4 w4 = Ws[k * 32 + c];
            const float x0 = Xs[(r     ) * DD + k];
            const float x1 = Xs[(r +  8) * DD + k];
            const float x2 = Xs[(r + 16) * DD + k];
            const float x3 = Xs[(r + 24) * DD + k];
            acc0.x += x0 * w4.x; acc0.y += x0 * w4.y; acc0.z += x0 * w4.z; acc0.w += x0 * w4.w;
            acc1.x += x1 * w4.x; acc1.y += x1 * w4.y; acc1.z += x1 * w4.z; acc1.w += x1 * w4.w;
            acc2.x += x2 * w4.x; acc2.y += x2 * w4.y; acc2.z += x2 * w4.z; acc2.w += x2 * w4.w;
            acc3.x += x3 * w4.x; acc3.y += x3 * w4.y; acc3.z += x3 * w4.z; acc3.w += x3 * w4.w;
        }

        float4 accs[4] = {acc0, acc1, acc2, acc3};
        #pragma unroll
        for (int m = 0; m < 4; m++) {
            const int row = row0 + r + 8 * m;
            __half2 h0 = __float22half2_rn(make_float2(accs[m].x, accs[m].y));
            __half2 h1 = __float22half2_rn(make_float2(accs[m].z, accs[m].w));
            uint2 hv;
            hv.x = *(unsigned*)&h0;
            hv.y = *(unsigned*)&h1;
            ((uint2*)(g_h16 + (size_t)row * DD))[c] = hv;
        }
    }
}

// ---------------------------------------------------------------------------
// agg — one warp per node:
// out[node] = b + dinv*(dinv*h16[node] + sum_e nm_e * h16[src_e]).  Pure store.
// ---------------------------------------------------------------------------
__global__ void k_agg(float* __restrict__ out, const float* __restrict__ b) {
    const int node = (blockIdx.x * blockDim.x + threadIdx.x) >> 5;
    const int lane = threadIdx.x & 31;
    if (node >= NN) return;

    const int beg = g_off[node];
    const int end = g_off[node + 1];
    const float dd = g_dinv[node];

    // self term: dd * h_self
    float4 acc;
    {
        const uint2 hv = ((const uint2*)(g_h16 + (size_t)node * DD))[lane];
        const float2 v0 = __half22float2(*(const __half2*)&hv.x);
        const float2 v1 = __half22float2(*(const __half2*)&hv.y);
        acc.x = dd * v0.x; acc.y = dd * v0.y;
        acc.z = dd * v1.x; acc.w = dd * v1.y;
    }

    #pragma unroll 4
    for (int e = beg; e < end; e++) {
        const int2  p  = g_csr[e];
        const float nm = __int_as_float(p.y);
        const uint2 hv = ((const uint2*)(g_h16 + (size_t)p.x * DD))[lane];
        const float2 v0 = __half22float2(*(const __half2*)&hv.x);
        const float2 v1 = __half22float2(*(const __half2*)&hv.y);
        acc.x += nm * v0.x;
        acc.y += nm * v0.y;
        acc.z += nm * v1.x;
        acc.w += nm * v1.y;
    }

    const float4 b4 = ((const float4*)b)[lane];
    float4 o;
    o.x = b4.x + dd * acc.x;
    o.y = b4.y + dd * acc.y;
    o.z = b4.z + dd * acc.z;
    o.w = b4.w + dd * acc.w;
    ((float4*)(out + (size_t)node * DD))[lane] = o;
}

// ---------------------------------------------------------------------------
extern "C" void kernel_launch(void* const* d_in, const int* in_sizes, int n_in,
                              void* d_out, int out_size) {
    const float* x  = nullptr;
    const int*   ei = nullptr;
    const float* ew = nullptr;
    const float* W  = nullptr;
    const float* b  = nullptr;
    int E = 0;
    for (int i = 0; i < n_in; i++) {
        const int sz = in_sizes[i];
        if      (sz == NN * DD)   x  = (const float*)d_in[i];
        else if (sz == 2 * EE)    ei = (const int*)d_in[i];
        else if (sz == EE)        { ew = (const float*)d_in[i]; E = sz; }
        else if (sz == DD * DD)   W  = (const float*)d_in[i];
        else if (sz == DD)        b  = (const float*)d_in[i];
    }
    if (!x || !ei || !ew || !W || !b) return;

    float* out = (float*)d_out;
    const int* src = ei;
    const int* dst = ei + E;
    const int E4 = E / 4;   // E = 3,200,000 divisible by 4

    // One-time setup (happens on the uncaptured correctness call)
    static cudaStream_t s2 = nullptr;
    static cudaEvent_t evFork = nullptr, evGemm = nullptr;
    static bool setup = false;
    if (!setup) {
        cudaFuncSetAttribute(k_gemm, cudaFuncAttributeMaxDynamicSharedMemorySize,
                             80 * 1024);
        cudaStreamCreateWithFlags(&s2, cudaStreamNonBlocking);
        cudaEventCreateWithFlags(&evFork, cudaEventDisableTiming);
        cudaEventCreateWithFlags(&evGemm, cudaEventDisableTiming);
        setup = true;
    }

    // Fork: GEMM on s2 (independent of edge chain)
    cudaEventRecord(evFork, 0);
    cudaStreamWaitEvent(s2, evFork, 0);
    k_gemm<<<296, 256, 80 * 1024, s2>>>(x, W);
    cudaEventRecord(evGemm, s2);

    // Edge chain on the main (captured) stream
    k_init<<<(NN + 255) / 256, 256>>>();
    k_deg_count<<<(E4 + 255) / 256, 256>>>(dst, ew, E4);
    k_scan1<<<SCAN_B, 1024>>>();
    k_scan2<<<1, 128>>>();
    k_scan3<<<SCAN_B, 1024>>>();
    k_fill<<<(E4 + 255) / 256, 256>>>(src, dst, ew, E4);

    // Join: agg needs both fill (main) and gemm (s2)
    cudaStreamWaitEvent(0, evGemm, 0);
    k_agg<<<(NN * 32 + 255) / 256, 256>>>(out, b);
}